// round 15
// baseline (speedup 1.0000x reference)
#include <cuda_runtime.h>
#include <cuda_fp16.h>
#include <cstdint>

// ---------------------------------------------------------------------------
// JointNetwork: out[b,t,u,:] = tanh(a[bt,:] + t[bu,:]) @ W_j + b_j
//   big GEMM: M=204800, K=640, N=512, fp32 out
// R14: main kernel 384 thr (12 warps, 3x4), CTA M96xN256, warp M32xN64,
//      explicit ks+1 fragment double-buffering (reg cap 170 allows it).
//      Prep (convert + HMMA proj) unchanged from R13.
// ---------------------------------------------------------------------------
#define HID   640
#define NCLS  512
#define M_TOT 204800

// fp16 scratch (device globals)
__device__ __half g_a[2048 * HID];    // audio projection out, fp16
__device__ __half g_t[448 * HID];     // text projection out, fp16 (padded)
__device__ __half g_wj[NCLS * HID];   // W_j^T [v][h], K-major rows
__device__ __half g_ah[2048 * 512];   // audio input, fp16
__device__ __half g_th[448 * 320];    // text input, fp16 (rows 400+ zero)
__device__ __half g_waT[HID * 512];   // W_a^T [n][k]
__device__ __half g_wtT[HID * 320];   // W_t^T [n][k]

// Main kernel SMEM: A stages 12KB @ {0,12K}; B stages 32KB @ {24K,56K}; 88KB
#define SA_STAGE(s) ((uint32_t)(s) * 12288u)
#define SB_STAGE(s) (24576u + (uint32_t)(s) * 32768u)
#define SMEM_BYTES  90112u

// ---------------------------------------------------------------------------
__device__ __forceinline__ uint32_t smem_u32(const void* p) {
    uint32_t a;
    asm("{ .reg .u64 t; cvta.to.shared.u64 t, %1; cvt.u32.u64 %0, t; }" : "=r"(a) : "l"(p));
    return a;
}
__device__ __forceinline__ uint32_t swz128(uint32_t off) { return off ^ ((off >> 3) & 0x70); }

__device__ __forceinline__ float tanh_fast(float x) {
    float e;
    asm("ex2.approx.f32 %0, %1;" : "=f"(e) : "f"(x * 2.8853900817779268f)); // e^{2x}
    float r;
    asm("rcp.approx.f32 %0, %1;" : "=f"(r) : "f"(e + 1.0f));
    return fmaf(-2.0f, r, 1.0f);
}

#define CP_ASYNC16(dst_u32, src_ptr) \
    asm volatile("cp.async.cg.shared.global [%0], [%1], 16;" \
        :: "r"(dst_u32), "l"(src_ptr) : "memory")
#define CP_ASYNC_COMMIT() asm volatile("cp.async.commit_group;" ::: "memory")
#define CP_ASYNC_WAIT0()  asm volatile("cp.async.wait_group 0;" ::: "memory")

#define LDSM_X4(r0, r1, r2, r3, addr) \
    asm volatile("ldmatrix.sync.aligned.m8n8.x4.shared.b16 {%0,%1,%2,%3}, [%4];" \
        : "=r"(r0), "=r"(r1), "=r"(r2), "=r"(r3) : "r"(addr))

#define MMA16816(d, a, b) \
    asm volatile("mma.sync.aligned.m16n8k16.row.col.f32.f16.f16.f32 " \
        "{%0,%1,%2,%3}, {%4,%5,%6,%7}, {%8,%9}, {%0,%1,%2,%3};" \
        : "+f"((d)[0]), "+f"((d)[1]), "+f"((d)[2]), "+f"((d)[3]) \
        : "r"((a)[0]), "r"((a)[1]), "r"((a)[2]), "r"((a)[3]), "r"((b)[0]), "r"((b)[1]))

// ---------------------------------------------------------------------------
// convert_kernel: fp32 -> fp16 copies / transposes (dest-linear indexing)
// ---------------------------------------------------------------------------
static constexpr int O1 = 1048576;            // 2048*512
static constexpr int O2 = O1 + 128000;        // + 400*320
static constexpr int O3 = O2 + 327680;        // + 640*512
static constexpr int O4 = O3 + 204800;        // + 640*320
static constexpr int CEND = O4 + 327680;      // + 512*640
static constexpr int CONV_BLOCKS = (CEND + 255) / 256;

__global__ __launch_bounds__(256) void convert_kernel(
    const float* __restrict__ audio, const float* __restrict__ text,
    const float* __restrict__ W_a, const float* __restrict__ W_t,
    const float* __restrict__ W_j)
{
    int idx = blockIdx.x * 256 + threadIdx.x;
    if (idx >= CEND) return;
    if (idx < O1) {
        g_ah[idx] = __float2half_rn(audio[idx]);
    } else if (idx < O2) {
        int d = idx - O1;
        g_th[d] = __float2half_rn(text[d]);
    } else if (idx < O3) {
        int d = idx - O2;
        int n = d / 512, k = d - n * 512;
        g_waT[d] = __float2half_rn(W_a[k * HID + n]);
    } else if (idx < O4) {
        int d = idx - O3;
        int n = d / 320, k = d - n * 320;
        g_wtT[d] = __float2half_rn(W_t[k * HID + n]);
    } else {
        int d = idx - O4;
        int v = d / HID, h = d - v * HID;
        g_wj[d] = __float2half_rn(W_j[h * NCLS + v]);
    }
}

// ---------------------------------------------------------------------------
// proj_kernel: C[M,HID] = A[M,K] @ W + bias (fp16 in/out, fp32 accum, HMMA)
//   CTA tile M64 x N128, 256 thr (8 warps, 2x4), warp tile M32 x N32.
// ---------------------------------------------------------------------------
__global__ __launch_bounds__(256) void proj_kernel(
    const float* __restrict__ b_a, const float* __restrict__ b_t)
{
    __shared__ __align__(1024) char psm[49152];
    const uint32_t sb = smem_u32(psm);
    const int tid  = threadIdx.x;
    const int lane = tid & 31;
    const int wid  = tid >> 5;
    const int warp_m = wid & 1;
    const int warp_n = wid >> 1;

    const __half* Ap; const __half* Wp; const float* bias; __half* Cp;
    int lda, Kd, kch, m0, n0;
    {
        int blk = blockIdx.x;
        if (blk < 160) {
            int my = blk / 5, nx = blk - my * 5;
            Ap = g_ah; lda = 512; Wp = g_waT; Kd = 512; kch = 8;
            bias = b_a; Cp = g_a; m0 = my * 64; n0 = nx * 128;
        } else {
            int b = blk - 160;
            int my = b / 5, nx = b - my * 5;
            Ap = g_th; lda = 320; Wp = g_wtT; Kd = 320; kch = 5;
            bias = b_t; Cp = g_t; m0 = my * 64; n0 = nx * 128;
        }
    }

    const int lr = tid >> 3;
    const int lj = tid & 7;
    const __half* a_src = Ap + (size_t)(m0 + lr) * lda + lj * 8;
    const __half* b_src = Wp + (size_t)(n0 + lr) * Kd + lj * 8;

    auto loadAB = [&](int kc, int s) {
        const int ko = kc * 64;
#pragma unroll
        for (int i = 0; i < 2; i++) {
            uint32_t off = (uint32_t)((lr + i * 32) * 128 + lj * 16);
            CP_ASYNC16(sb + (uint32_t)(s * 8192) + swz128(off),
                       a_src + (size_t)i * 32 * lda + ko);
        }
#pragma unroll
        for (int i = 0; i < 4; i++) {
            uint32_t off = (uint32_t)((lr + i * 32) * 128 + lj * 16);
            CP_ASYNC16(sb + 16384u + (uint32_t)(s * 16384) + swz128(off),
                       b_src + (size_t)i * 32 * Kd + ko);
        }
        CP_ASYNC_COMMIT();
    };

    uint32_t offA[2], offB[2];
    {
        const int tl = lane >> 3, rr = lane & 7;
#pragma unroll
        for (int mt = 0; mt < 2; mt++) {
            int row = warp_m * 32 + mt * 16 + (lane & 15);
            offA[mt] = swz128((uint32_t)(row * 128 + (lane >> 4) * 16));
        }
#pragma unroll
        for (int p = 0; p < 2; p++) {
            int row = warp_n * 32 + p * 16 + (tl >> 1) * 8 + rr;
            offB[p] = swz128((uint32_t)(row * 128 + (tl & 1) * 16));
        }
    }

    float acc[2][4][4];
#pragma unroll
    for (int mt = 0; mt < 2; mt++)
#pragma unroll
        for (int nt = 0; nt < 4; nt++)
#pragma unroll
            for (int q = 0; q < 4; q++) acc[mt][nt][q] = 0.f;

    loadAB(0, 0);
    for (int c = 0; c < kch; c++) {
        const int s = c & 1;
        CP_ASYNC_WAIT0();
        __syncthreads();
        if (c + 1 < kch) loadAB(c + 1, s ^ 1);

        const uint32_t aBase = sb + (uint32_t)(s * 8192);
        const uint32_t bBase = sb + 16384u + (uint32_t)(s * 16384);
#pragma unroll
        for (int ks = 0; ks < 4; ks++) {
            const uint32_t kso = (uint32_t)ks * 32u;
            uint32_t afr[2][4];
#pragma unroll
            for (int mt = 0; mt < 2; mt++)
                LDSM_X4(afr[mt][0], afr[mt][1], afr[mt][2], afr[mt][3],
                        aBase + (offA[mt] ^ kso));
            uint32_t bfr[4][2];
#pragma unroll
            for (int p = 0; p < 2; p++) {
                uint32_t r0, r1, r2, r3;
                LDSM_X4(r0, r1, r2, r3, bBase + (offB[p] ^ kso));
                bfr[p * 2 + 0][0] = r0; bfr[p * 2 + 0][1] = r1;
                bfr[p * 2 + 1][0] = r2; bfr[p * 2 + 1][1] = r3;
            }
#pragma unroll
            for (int mt = 0; mt < 2; mt++)
#pragma unroll
                for (int nt = 0; nt < 4; nt++)
                    MMA16816(acc[mt][nt], afr[mt], bfr[nt]);
        }
    }

#pragma unroll
    for (int nt = 0; nt < 4; nt++) {
        int col = n0 + warp_n * 32 + nt * 8 + (lane & 3) * 2;
        float bj0 = bias[col], bj1 = bias[col + 1];
#pragma unroll
        for (int mt = 0; mt < 2; mt++) {
            int r0 = m0 + warp_m * 32 + mt * 16 + (lane >> 2);
            __half2* p0 = (__half2*)(Cp + (size_t)r0 * HID + col);
            __half2* p1 = (__half2*)(Cp + (size_t)(r0 + 8) * HID + col);
            *p0 = __floats2half2_rn(acc[mt][nt][0] + bj0, acc[mt][nt][1] + bj1);
            *p1 = __floats2half2_rn(acc[mt][nt][2] + bj0, acc[mt][nt][3] + bj1);
        }
    }
}

// ---------------------------------------------------------------------------
// Main HMMA kernel: 384 thr (12 warps, warp_m = wid>>2 in 0..2,
// warp_n = wid&3 in 0..3), CTA tile M96 x N256, warp tile M32 x N64,
// K in 10 chunks of 64, SMEM double-buffered, FRAGMENTS double-buffered.
// ---------------------------------------------------------------------------
static constexpr int THREADS = 384;
static constexpr int KCHUNKS = 10;

__global__ __launch_bounds__(THREADS, 1) void joint_main_kernel(
    const float* __restrict__ b_j, float* __restrict__ out)
{
    extern __shared__ __align__(1024) char smem[];
    const uint32_t sb = smem_u32(smem);
    const int tid  = threadIdx.x;
    const int lane = tid & 31;
    const int wid  = tid >> 5;
    const int warp_m = wid >> 2;   // 0..2 (32-row slab)
    const int warp_n = wid & 3;    // 0..3 (64-col slab)
    const int m0 = blockIdx.x * 96;
    const int n0 = blockIdx.y * 256;

    // producer: 768 16B tasks (96 rows x 8 units), 2 per thread
    const int pr0 = tid >> 3,         pj0 = tid & 7;
    const int pr1 = (tid + 384) >> 3, pj1 = (tid + 384) & 7;
    int mc0 = m0 + pr0; if (mc0 > M_TOT - 1) mc0 = M_TOT - 1;
    int mc1 = m0 + pr1; if (mc1 > M_TOT - 1) mc1 = M_TOT - 1;
    const int bt0 = mc0 / 100, u0 = mc0 - bt0 * 100;
    const int bt1 = mc1 / 100, u1 = mc1 - bt1 * 100;
    const __half* rowa0 = g_a + bt0 * HID + pj0 * 8;
    const __half* rowt0 = g_t + (((bt0 >> 9) * 100) + u0) * HID + pj0 * 8;
    const __half* rowa1 = g_a + bt1 * HID + pj1 * 8;
    const __half* rowt1 = g_t + (((bt1 >> 9) * 100) + u1) * HID + pj1 * 8;
    const uint32_t soff0 = swz128((uint32_t)(pr0 * 128 + pj0 * 16));
    const uint32_t soff1 = swz128((uint32_t)(pr1 * 128 + pj1 * 16));

    // precomputed swizzled LDSM offsets; swz(off + ks*32) = swz(off) ^ (ks*32)
    uint32_t offA[2], offB[4];
    {
        const int tl = lane >> 3, rr = lane & 7;
#pragma unroll
        for (int mt = 0; mt < 2; mt++) {
            int row = warp_m * 32 + mt * 16 + (lane & 15);
            offA[mt] = swz128((uint32_t)(row * 128 + (lane >> 4) * 16));
        }
#pragma unroll
        for (int p = 0; p < 4; p++) {
            int row = warp_n * 64 + p * 16 + (tl >> 1) * 8 + rr;
            offB[p] = swz128((uint32_t)(row * 128 + (tl & 1) * 16));
        }
    }

    float acc[2][8][4];
#pragma unroll
    for (int mt = 0; mt < 2; mt++)
#pragma unroll
        for (int nt = 0; nt < 8; nt++)
#pragma unroll
            for (int q = 0; q < 4; q++) acc[mt][nt][q] = 0.f;

    // double-buffered fragments (ks+1 prefetch)
    uint32_t afr[2][2][4];
    uint32_t bfr[2][8][2];

    auto loadB = [&](int c, int s) {
        const __half* base = g_wj + (size_t)n0 * HID + c * 64;
        for (int i = tid; i < 2048; i += THREADS) {   // 256 rows x 8 units
            int row = i >> 3, unit = i & 7;
            uint32_t off = (uint32_t)(row * 128 + unit * 16);
            CP_ASYNC16(sb + SB_STAGE(s) + swz128(off),
                       base + (size_t)row * HID + unit * 8);
        }
        CP_ASYNC_COMMIT();
    };

    auto tanh_store = [&](uint4 av, uint4 tv, uint32_t soff, int s) {
        const __half2* ah = (const __half2*)&av;
        const __half2* th = (const __half2*)&tv;
        uint32_t rs[4];
#pragma unroll
        for (int q = 0; q < 4; q++) {
            float2 af = __half22float2(ah[q]);
            float2 tf = __half22float2(th[q]);
            __half2 h = __floats2half2_rn(tanh_fast(af.x + tf.x), tanh_fast(af.y + tf.y));
            rs[q] = *(uint32_t*)&h;
        }
        *(uint4*)(smem + SA_STAGE(s) + soff) = make_uint4(rs[0], rs[1], rs[2], rs[3]);
    };

    // ---- prologue: produce chunk 0 (both tasks), start B chunk 0 ----
    {
        uint4 a0 = *(const uint4*)rowa0, t0v = *(const uint4*)rowt0;
        uint4 a1 = *(const uint4*)rowa1, t1v = *(const uint4*)rowt1;
        tanh_store(a0, t0v, soff0, 0);
        tanh_store(a1, t1v, soff1, 0);
    }
    loadB(0, 0);

    // ---- main loop ----
    for (int c = 0; c < KCHUNKS; c++) {
        const int s = c & 1;
        CP_ASYNC_WAIT0();
        __syncthreads();                 // stage s ready; stage s^1 free

        const bool more = (c + 1 < KCHUNKS);
        if (more) loadB(c + 1, s ^ 1);

        uint4 av0, tv0, av1, tv1;
        if (more) {
            av0 = *(const uint4*)(rowa0 + (c + 1) * 64);
            tv0 = *(const uint4*)(rowt0 + (c + 1) * 64);
            av1 = *(const uint4*)(rowa1 + (c + 1) * 64);
            tv1 = *(const uint4*)(rowt1 + (c + 1) * 64);
        }

        const uint32_t aBase = sb + SA_STAGE(s);
        const uint32_t bBase = sb + SB_STAGE(s);

        // fragment loader for one ks into buffer buf
        auto load_frags = [&](int ks, int buf) {
            const uint32_t kso = (uint32_t)ks * 32u;
#pragma unroll
            for (int mt = 0; mt < 2; mt++)
                LDSM_X4(afr[buf][mt][0], afr[buf][mt][1], afr[buf][mt][2], afr[buf][mt][3],
                        aBase + (offA[mt] ^ kso));
#pragma unroll
            for (int p = 0; p < 4; p++) {
                uint32_t r0, r1, r2, r3;
                LDSM_X4(r0, r1, r2, r3, bBase + (offB[p] ^ kso));
                bfr[buf][p * 2 + 0][0] = r0; bfr[buf][p * 2 + 0][1] = r1;
                bfr[buf][p * 2 + 1][0] = r2; bfr[buf][p * 2 + 1][1] = r3;
            }
        };

        load_frags(0, 0);
#pragma unroll
        for (int ks = 0; ks < 4; ks++) {
            const int cur = ks & 1;
            if (ks < 3) load_frags(ks + 1, cur ^ 1);   // prefetch next ks

#pragma unroll
            for (int mt = 0; mt < 2; mt++)
#pragma unroll
                for (int nt = 0; nt < 8; nt++)
                    MMA16816(acc[mt][nt], afr[cur][mt], bfr[cur][nt]);

            if (ks == 1 && more) tanh_store(av0, tv0, soff0, s ^ 1);
            if (ks == 2 && more) tanh_store(av1, tv1, soff1, s ^ 1);
        }
    }

    // ---- epilogue: + bias, fp32 stores (row-guarded for padded last tile) ----
#pragma unroll
    for (int nt = 0; nt < 8; nt++) {
        int col = n0 + warp_n * 64 + nt * 8 + (lane & 3) * 2;
        float bj0 = b_j[col], bj1 = b_j[col + 1];
#pragma unroll
        for (int mt = 0; mt < 2; mt++) {
            int r0 = m0 + warp_m * 32 + mt * 16 + (lane >> 2);
            float* p = out + (size_t)r0 * NCLS + col;
            if (r0 < M_TOT)
                *(float2*)p = make_float2(acc[mt][nt][0] + bj0, acc[mt][nt][1] + bj1);
            if (r0 + 8 < M_TOT)
                *(float2*)(p + 8 * NCLS) =
                    make_float2(acc[mt][nt][2] + bj0, acc[mt][nt][3] + bj1);
        }
    }
}

// ---------------------------------------------------------------------------
extern "C" void kernel_launch(void* const* d_in, const int* in_sizes, int n_in,
                              void* d_out, int out_size) {
    const float* audio = (const float*)d_in[0];
    const float* text  = (const float*)d_in[1];
    const float* W_a   = (const float*)d_in[2];
    const float* b_a   = (const float*)d_in[3];
    const float* W_t   = (const float*)d_in[4];
    const float* b_t   = (const float*)d_in[5];
    const float* W_j   = (const float*)d_in[6];
    const float* b_j   = (const float*)d_in[7];
    float* out = (float*)d_out;

    convert_kernel<<<CONV_BLOCKS, 256>>>(audio, text, W_a, W_t, W_j);
    proj_kernel<<<195, 256>>>(b_a, b_t);

    cudaFuncSetAttribute(joint_main_kernel, cudaFuncAttributeMaxDynamicSharedMemorySize,
                         SMEM_BYTES);
    joint_main_kernel<<<dim3(2134, 2), THREADS, SMEM_BYTES>>>(b_j, out);
}

// round 17
// speedup vs baseline: 1.2395x; 1.2395x over previous
#include <cuda_runtime.h>
#include <cuda_fp16.h>
#include <cstdint>

// ---------------------------------------------------------------------------
// JointNetwork: out[b,t,u,:] = tanh(a[bt,:] + t[bu,:]) @ W_j + b_j
//   big GEMM: M=204800, K=640, N=512, fp32 out
// R15: REVERT main to R12 config (best known: 455us main).
//      Lesson bank: reg-funded ILP beyond 128regs/512thr always spills (R9,R14).
//      Prep: convert flat copies vectorized float4->half4.
// ---------------------------------------------------------------------------
#define HID   640
#define NCLS  512

// fp16 scratch (device globals)
__device__ __half g_a[2048 * HID];    // audio projection out, fp16
__device__ __half g_t[448 * HID];     // text projection out, fp16 (padded)
__device__ __half g_wj[NCLS * HID];   // W_j^T [v][h], K-major rows
__device__ __half g_ah[2048 * 512];   // audio input, fp16
__device__ __half g_th[448 * 320];    // text input, fp16 (rows 400+ zero)
__device__ __half g_waT[HID * 512];   // W_a^T [n][k]
__device__ __half g_wtT[HID * 320];   // W_t^T [n][k]

// Main kernel SMEM: A stages 8KB @ {0,8K}; B stages 64KB @ {16K,80K}; 144KB
#define SA_STAGE(s) ((uint32_t)(s) * 8192u)
#define SB_STAGE(s) (16384u + (uint32_t)(s) * 65536u)
#define SMEM_BYTES  147456u

// ---------------------------------------------------------------------------
__device__ __forceinline__ uint32_t smem_u32(const void* p) {
    uint32_t a;
    asm("{ .reg .u64 t; cvta.to.shared.u64 t, %1; cvt.u32.u64 %0, t; }" : "=r"(a) : "l"(p));
    return a;
}
__device__ __forceinline__ uint32_t swz128(uint32_t off) { return off ^ ((off >> 3) & 0x70); }

__device__ __forceinline__ float tanh_fast(float x) {
    float e;
    asm("ex2.approx.f32 %0, %1;" : "=f"(e) : "f"(x * 2.8853900817779268f)); // e^{2x}
    float r;
    asm("rcp.approx.f32 %0, %1;" : "=f"(r) : "f"(e + 1.0f));
    return fmaf(-2.0f, r, 1.0f);
}

#define CP_ASYNC16(dst_u32, src_ptr) \
    asm volatile("cp.async.cg.shared.global [%0], [%1], 16;" \
        :: "r"(dst_u32), "l"(src_ptr) : "memory")
#define CP_ASYNC_COMMIT() asm volatile("cp.async.commit_group;" ::: "memory")
#define CP_ASYNC_WAIT0()  asm volatile("cp.async.wait_group 0;" ::: "memory")

#define LDSM_X4(r0, r1, r2, r3, addr) \
    asm volatile("ldmatrix.sync.aligned.m8n8.x4.shared.b16 {%0,%1,%2,%3}, [%4];" \
        : "=r"(r0), "=r"(r1), "=r"(r2), "=r"(r3) : "r"(addr))

#define MMA16816(d, a, b) \
    asm volatile("mma.sync.aligned.m16n8k16.row.col.f32.f16.f16.f32 " \
        "{%0,%1,%2,%3}, {%4,%5,%6,%7}, {%8,%9}, {%0,%1,%2,%3};" \
        : "+f"((d)[0]), "+f"((d)[1]), "+f"((d)[2]), "+f"((d)[3]) \
        : "r"((a)[0]), "r"((a)[1]), "r"((a)[2]), "r"((a)[3]), "r"((b)[0]), "r"((b)[1]))

// ---------------------------------------------------------------------------
// convert_kernel: fp32 -> fp16.
//   Vectorized flat copies: audio 262144 v4-tasks, text 32000 v4-tasks.
//   Elementwise transposes: W_a^T 327680, W_t^T 204800, W_j^T 327680.
//   Task index space: [0,V1) audio-v4; [V1,V2) text-v4; [V2,V3) WaT;
//                     [V3,V4) WtT; [V4,VEND) WjT
// ---------------------------------------------------------------------------
static constexpr int V1 = 262144;             // 2048*512/4
static constexpr int V2 = V1 + 32000;         // + 400*320/4
static constexpr int V3 = V2 + 327680;        // + 640*512
static constexpr int V4 = V3 + 204800;        // + 640*320
static constexpr int VEND = V4 + 327680;      // + 512*640
static constexpr int CONV_BLOCKS = (VEND + 255) / 256;

__global__ __launch_bounds__(256) void convert_kernel(
    const float* __restrict__ audio, const float* __restrict__ text,
    const float* __restrict__ W_a, const float* __restrict__ W_t,
    const float* __restrict__ W_j)
{
    int idx = blockIdx.x * 256 + threadIdx.x;
    if (idx >= VEND) return;
    if (idx < V1) {
        float4 v = *(const float4*)(audio + (size_t)idx * 4);
        __half2 h0 = __floats2half2_rn(v.x, v.y);
        __half2 h1 = __floats2half2_rn(v.z, v.w);
        *(uint2*)(g_ah + (size_t)idx * 4) =
            make_uint2(*(uint32_t*)&h0, *(uint32_t*)&h1);
    } else if (idx < V2) {
        int d = idx - V1;
        float4 v = *(const float4*)(text + (size_t)d * 4);
        __half2 h0 = __floats2half2_rn(v.x, v.y);
        __half2 h1 = __floats2half2_rn(v.z, v.w);
        *(uint2*)(g_th + (size_t)d * 4) =
            make_uint2(*(uint32_t*)&h0, *(uint32_t*)&h1);
    } else if (idx < V3) {
        int d = idx - V2;
        int n = d / 512, k = d - n * 512;
        g_waT[d] = __float2half_rn(W_a[k * HID + n]);
    } else if (idx < V4) {
        int d = idx - V3;
        int n = d / 320, k = d - n * 320;
        g_wtT[d] = __float2half_rn(W_t[k * HID + n]);
    } else {
        int d = idx - V4;
        int v = d / HID, h = d - v * HID;
        g_wj[d] = __float2half_rn(W_j[h * NCLS + v]);
    }
}

// ---------------------------------------------------------------------------
// proj_kernel: C[M,HID] = A[M,K] @ W + bias (fp16 in/out, fp32 accum, HMMA)
//   CTA tile M64 x N128, 256 thr (8 warps, 2x4), warp tile M32 x N32.
// ---------------------------------------------------------------------------
__global__ __launch_bounds__(256) void proj_kernel(
    const float* __restrict__ b_a, const float* __restrict__ b_t)
{
    __shared__ __align__(1024) char psm[49152];
    const uint32_t sb = smem_u32(psm);
    const int tid  = threadIdx.x;
    const int lane = tid & 31;
    const int wid  = tid >> 5;
    const int warp_m = wid & 1;
    const int warp_n = wid >> 1;

    const __half* Ap; const __half* Wp; const float* bias; __half* Cp;
    int lda, Kd, kch, m0, n0;
    {
        int blk = blockIdx.x;
        if (blk < 160) {
            int my = blk / 5, nx = blk - my * 5;
            Ap = g_ah; lda = 512; Wp = g_waT; Kd = 512; kch = 8;
            bias = b_a; Cp = g_a; m0 = my * 64; n0 = nx * 128;
        } else {
            int b = blk - 160;
            int my = b / 5, nx = b - my * 5;
            Ap = g_th; lda = 320; Wp = g_wtT; Kd = 320; kch = 5;
            bias = b_t; Cp = g_t; m0 = my * 64; n0 = nx * 128;
        }
    }

    const int lr = tid >> 3;
    const int lj = tid & 7;
    const __half* a_src = Ap + (size_t)(m0 + lr) * lda + lj * 8;
    const __half* b_src = Wp + (size_t)(n0 + lr) * Kd + lj * 8;

    auto loadAB = [&](int kc, int s) {
        const int ko = kc * 64;
#pragma unroll
        for (int i = 0; i < 2; i++) {
            uint32_t off = (uint32_t)((lr + i * 32) * 128 + lj * 16);
            CP_ASYNC16(sb + (uint32_t)(s * 8192) + swz128(off),
                       a_src + (size_t)i * 32 * lda + ko);
        }
#pragma unroll
        for (int i = 0; i < 4; i++) {
            uint32_t off = (uint32_t)((lr + i * 32) * 128 + lj * 16);
            CP_ASYNC16(sb + 16384u + (uint32_t)(s * 16384) + swz128(off),
                       b_src + (size_t)i * 32 * Kd + ko);
        }
        CP_ASYNC_COMMIT();
    };

    uint32_t offA[2], offB[2];
    {
        const int tl = lane >> 3, rr = lane & 7;
#pragma unroll
        for (int mt = 0; mt < 2; mt++) {
            int row = warp_m * 32 + mt * 16 + (lane & 15);
            offA[mt] = swz128((uint32_t)(row * 128 + (lane >> 4) * 16));
        }
#pragma unroll
        for (int p = 0; p < 2; p++) {
            int row = warp_n * 32 + p * 16 + (tl >> 1) * 8 + rr;
            offB[p] = swz128((uint32_t)(row * 128 + (tl & 1) * 16));
        }
    }

    float acc[2][4][4];
#pragma unroll
    for (int mt = 0; mt < 2; mt++)
#pragma unroll
        for (int nt = 0; nt < 4; nt++)
#pragma unroll
            for (int q = 0; q < 4; q++) acc[mt][nt][q] = 0.f;

    loadAB(0, 0);
    for (int c = 0; c < kch; c++) {
        const int s = c & 1;
        CP_ASYNC_WAIT0();
        __syncthreads();
        if (c + 1 < kch) loadAB(c + 1, s ^ 1);

        const uint32_t aBase = sb + (uint32_t)(s * 8192);
        const uint32_t bBase = sb + 16384u + (uint32_t)(s * 16384);
#pragma unroll
        for (int ks = 0; ks < 4; ks++) {
            const uint32_t kso = (uint32_t)ks * 32u;
            uint32_t afr[2][4];
#pragma unroll
            for (int mt = 0; mt < 2; mt++)
                LDSM_X4(afr[mt][0], afr[mt][1], afr[mt][2], afr[mt][3],
                        aBase + (offA[mt] ^ kso));
            uint32_t bfr[4][2];
#pragma unroll
            for (int p = 0; p < 2; p++) {
                uint32_t r0, r1, r2, r3;
                LDSM_X4(r0, r1, r2, r3, bBase + (offB[p] ^ kso));
                bfr[p * 2 + 0][0] = r0; bfr[p * 2 + 0][1] = r1;
                bfr[p * 2 + 1][0] = r2; bfr[p * 2 + 1][1] = r3;
            }
#pragma unroll
            for (int mt = 0; mt < 2; mt++)
#pragma unroll
                for (int nt = 0; nt < 4; nt++)
                    MMA16816(acc[mt][nt], afr[mt], bfr[nt]);
        }
    }

#pragma unroll
    for (int nt = 0; nt < 4; nt++) {
        int col = n0 + warp_n * 32 + nt * 8 + (lane & 3) * 2;
        float bj0 = bias[col], bj1 = bias[col + 1];
#pragma unroll
        for (int mt = 0; mt < 2; mt++) {
            int r0 = m0 + warp_m * 32 + mt * 16 + (lane >> 2);
            __half2* p0 = (__half2*)(Cp + (size_t)r0 * HID + col);
            __half2* p1 = (__half2*)(Cp + (size_t)(r0 + 8) * HID + col);
            *p0 = __floats2half2_rn(acc[mt][nt][0] + bj0, acc[mt][nt][1] + bj1);
            *p1 = __floats2half2_rn(acc[mt][nt][2] + bj0, acc[mt][nt][3] + bj1);
        }
    }
}

// ---------------------------------------------------------------------------
// Main HMMA kernel (EXACT R12 config — best known: 455us):
// 512 thr (16 warps, 2x8), CTA tile M64 x N512, warp tile M32 x N64,
// K in 10 chunks of 64, double-buffered.
// ---------------------------------------------------------------------------
static constexpr int THREADS = 512;
static constexpr int KCHUNKS = 10;

__global__ __launch_bounds__(THREADS, 1) void joint_main_kernel(
    const float* __restrict__ b_j, float* __restrict__ out)
{
    extern __shared__ __align__(1024) char smem[];
    const uint32_t sb = smem_u32(smem);
    const int tid  = threadIdx.x;
    const int lane = tid & 31;
    const int wid  = tid >> 5;
    const int warp_m = wid & 1;    // 0..1 (32-row slab)
    const int warp_n = wid >> 1;   // 0..7 (64-col slab)
    const int m0 = blockIdx.x * 64;

    // producer: 512 tasks of 16B (64 rows x 8 units); one per thread
    const int pr = tid >> 3;
    const int pj = tid & 7;
    const int m   = m0 + pr;
    const int bt  = m / 100;
    const int u   = m - bt * 100;
    const __half* rowa = g_a + bt * HID + pj * 8;
    const __half* rowt = g_t + (((bt >> 9) * 100) + u) * HID + pj * 8;
    const uint32_t a_soff = swz128((uint32_t)(pr * 128 + pj * 16));

    // B cp.async mapping: 8 x 16B per thread per chunk
    const int b_row0  = tid >> 3;
    const int b_chunk = tid & 7;
    const __half* wj_base = g_wj + (size_t)b_row0 * HID + b_chunk * 8;

    // precomputed swizzled LDSM offsets; swz(off + ks*32) = swz(off) ^ (ks*32)
    uint32_t offA[2], offB[4];
    {
        const int tl = lane >> 3, rr = lane & 7;
#pragma unroll
        for (int mt = 0; mt < 2; mt++) {
            int row = warp_m * 32 + mt * 16 + (lane & 15);
            offA[mt] = swz128((uint32_t)(row * 128 + (lane >> 4) * 16));
        }
#pragma unroll
        for (int p = 0; p < 4; p++) {
            int row = warp_n * 64 + p * 16 + (tl >> 1) * 8 + rr;
            offB[p] = swz128((uint32_t)(row * 128 + (tl & 1) * 16));
        }
    }

    float acc[2][8][4];
#pragma unroll
    for (int mt = 0; mt < 2; mt++)
#pragma unroll
        for (int nt = 0; nt < 8; nt++)
#pragma unroll
            for (int q = 0; q < 4; q++) acc[mt][nt][q] = 0.f;

    auto loadB = [&](int c, int s) {
        const __half* src = wj_base + c * 64;
#pragma unroll
        for (int i = 0; i < 8; i++) {
            uint32_t off = (uint32_t)((b_row0 + i * 64) * 128 + b_chunk * 16);
            CP_ASYNC16(sb + SB_STAGE(s) + swz128(off), src + (size_t)i * 64 * HID);
        }
        CP_ASYNC_COMMIT();
    };

    auto tanh_store = [&](uint4 av, uint4 tv, int s) {
        const __half2* ah = (const __half2*)&av;
        const __half2* th = (const __half2*)&tv;
        uint32_t rs[4];
#pragma unroll
        for (int q = 0; q < 4; q++) {
            float2 af = __half22float2(ah[q]);
            float2 tf = __half22float2(th[q]);
            __half2 h = __floats2half2_rn(tanh_fast(af.x + tf.x), tanh_fast(af.y + tf.y));
            rs[q] = *(uint32_t*)&h;
        }
        *(uint4*)(smem + SA_STAGE(s) + a_soff) = make_uint4(rs[0], rs[1], rs[2], rs[3]);
    };

    {
        uint4 av = *(const uint4*)rowa;
        uint4 tv = *(const uint4*)rowt;
        tanh_store(av, tv, 0);
    }
    loadB(0, 0);

    for (int c = 0; c < KCHUNKS; c++) {
        const int s = c & 1;
        CP_ASYNC_WAIT0();
        __syncthreads();

        const bool more = (c + 1 < KCHUNKS);
        if (more) loadB(c + 1, s ^ 1);

        uint4 av, tv;
        if (more) {
            av = *(const uint4*)(rowa + (c + 1) * 64);
            tv = *(const uint4*)(rowt + (c + 1) * 64);
        }

        const uint32_t aBase = sb + SA_STAGE(s);
        const uint32_t bBase = sb + SB_STAGE(s);

#pragma unroll
        for (int ks = 0; ks < 4; ks++) {
            const uint32_t kso = (uint32_t)ks * 32u;
            uint32_t afr[2][4];
#pragma unroll
            for (int mt = 0; mt < 2; mt++)
                LDSM_X4(afr[mt][0], afr[mt][1], afr[mt][2], afr[mt][3],
                        aBase + (offA[mt] ^ kso));
            uint32_t bfr[8][2];
#pragma unroll
            for (int p = 0; p < 4; p++) {
                uint32_t r0, r1, r2, r3;
                LDSM_X4(r0, r1, r2, r3, bBase + (offB[p] ^ kso));
                bfr[p * 2 + 0][0] = r0; bfr[p * 2 + 0][1] = r1;
                bfr[p * 2 + 1][0] = r2; bfr[p * 2 + 1][1] = r3;
            }

#pragma unroll
            for (int mt = 0; mt < 2; mt++)
#pragma unroll
                for (int nt = 0; nt < 8; nt++)
                    MMA16816(acc[mt][nt], afr[mt], bfr[nt]);

            if (ks == 1 && more) tanh_store(av, tv, s ^ 1);
        }
    }

    // epilogue: + bias, fp32 stores
#pragma unroll
    for (int nt = 0; nt < 8; nt++) {
        int col = warp_n * 64 + nt * 8 + (lane & 3) * 2;
        float bj0 = b_j[col], bj1 = b_j[col + 1];
#pragma unroll
        for (int mt = 0; mt < 2; mt++) {
            int r0 = m0 + warp_m * 32 + mt * 16 + (lane >> 2);
            float* p = out + (size_t)r0 * NCLS + col;
            *(float2*)p              = make_float2(acc[mt][nt][0] + bj0, acc[mt][nt][1] + bj1);
            *(float2*)(p + 8 * NCLS) = make_float2(acc[mt][nt][2] + bj0, acc[mt][nt][3] + bj1);
        }
    }
}

// ---------------------------------------------------------------------------
extern "C" void kernel_launch(void* const* d_in, const int* in_sizes, int n_in,
                              void* d_out, int out_size) {
    const float* audio = (const float*)d_in[0];
    const float* text  = (const float*)d_in[1];
    const float* W_a   = (const float*)d_in[2];
    const float* b_a   = (const float*)d_in[3];
    const float* W_t   = (const float*)d_in[4];
    const float* b_t   = (const float*)d_in[5];
    const float* W_j   = (const float*)d_in[6];
    const float* b_j   = (const float*)d_in[7];
    float* out = (float*)d_out;

    convert_kernel<<<CONV_BLOCKS, 256>>>(audio, text, W_a, W_t, W_j);
    proj_kernel<<<195, 256>>>(b_a, b_t);

    cudaFuncSetAttribute(joint_main_kernel, cudaFuncAttributeMaxDynamicSharedMemorySize,
                         SMEM_BYTES);
    joint_main_kernel<<<3200, THREADS, SMEM_BYTES>>>(b_j, out);
}